// round 1
// baseline (speedup 1.0000x reference)
#include <cuda_runtime.h>

#define N_NODES 50000
#define N_EDGES 200000
#define IN_C    32
#define HID     32
#define OUT_C   16
#define EDGE_DIM 8
#define LN_EPS  1e-5f

// scatter-add accumulator (device global: no allocation allowed)
__device__ float g_agg[N_NODES * HID];

__global__ void zero_agg_kernel() {
    int i = blockIdx.x * blockDim.x + threadIdx.x;
    int stride = gridDim.x * blockDim.x;
    for (; i < N_NODES * HID; i += stride) g_agg[i] = 0.0f;
}

// ---------------------------------------------------------------------------
// Edge kernel: per-edge W = relu(ea @ nn_w + nn_b)  [32x32], msg = x[src] @ W,
// atomicAdd(msg) into g_agg[dst].
// Warp layout: lane = output channel o (0..31). Each warp processes a group of
// 4 edges so the smem reads of nn_w are amortized 4x.
// smem w layout: sw[(i*8+d)*32 + o]  -> lane-consecutive, conflict-free.
// ---------------------------------------------------------------------------
__global__ __launch_bounds__(256) void edge_kernel(
    const float* __restrict__ x,
    const int*   __restrict__ edge_index,
    const float* __restrict__ edge_attr,
    const float* __restrict__ nn_w,
    const float* __restrict__ nn_b)
{
    __shared__ float sw[IN_C * EDGE_DIM * HID];  // 8192 floats = 32 KB
    __shared__ float sb[IN_C * HID];             // 1024 floats =  4 KB
    __shared__ float xs_s[8][4][HID];            // per-warp x[src] staging

    const int tid = threadIdx.x;

    // Load + transpose nn_w: global [d][i*32+o] -> smem [(i*8+d)*32+o].
    // Consecutive tid -> consecutive o within an i-block: conflict-free STS.
    for (int idx = tid; idx < IN_C * EDGE_DIM * HID; idx += 256) {
        int d = idx >> 10;       // / 1024
        int j = idx & 1023;
        int i = j >> 5;
        int o = j & 31;
        sw[(i * EDGE_DIM + d) * HID + o] = nn_w[idx];
    }
    for (int idx = tid; idx < IN_C * HID; idx += 256) sb[idx] = nn_b[idx];
    __syncthreads();

    const int lane  = tid & 31;
    const int warp  = tid >> 5;
    const int gwarp = blockIdx.x * 8 + warp;
    const int warpsTotal = gridDim.x * 8;
    const int nGroups = N_EDGES / 4;   // 200000 / 4 = 50000, exact

    for (int g = gwarp; g < nGroups; g += warpsTotal) {
        const int e0 = g * 4;
        int dst[4];
        float ea[4][8];
        #pragma unroll
        for (int e = 0; e < 4; ++e) {
            int srce = edge_index[e0 + e];
            dst[e]   = edge_index[N_EDGES + e0 + e];
            const float4 lo = *(const float4*)(edge_attr + (size_t)(e0 + e) * EDGE_DIM);
            const float4 hi = *(const float4*)(edge_attr + (size_t)(e0 + e) * EDGE_DIM + 4);
            ea[e][0] = lo.x; ea[e][1] = lo.y; ea[e][2] = lo.z; ea[e][3] = lo.w;
            ea[e][4] = hi.x; ea[e][5] = hi.y; ea[e][6] = hi.z; ea[e][7] = hi.w;
            // coalesced gather of source-node row
            xs_s[warp][e][lane] = x[(size_t)srce * IN_C + lane];
        }
        __syncwarp();

        float msg[4] = {0.f, 0.f, 0.f, 0.f};

        #pragma unroll 8
        for (int i = 0; i < IN_C; ++i) {
            float w[8];
            #pragma unroll
            for (int d = 0; d < 8; ++d) w[d] = sw[(i * 8 + d) * HID + lane];
            const float b = sb[i * HID + lane];
            float xv[4];
            #pragma unroll
            for (int e = 0; e < 4; ++e) xv[e] = xs_s[warp][e][i];  // broadcast
            #pragma unroll
            for (int e = 0; e < 4; ++e) {
                float a = b;
                #pragma unroll
                for (int d = 0; d < 8; ++d) a = fmaf(ea[e][d], w[d], a);
                a = fmaxf(a, 0.f);                 // relu -> W[e][i][lane]
                msg[e] = fmaf(xv[e], a, msg[e]);   // contract with x[src]
            }
        }

        #pragma unroll
        for (int e = 0; e < 4; ++e)
            atomicAdd(&g_agg[(size_t)dst[e] * HID + lane], msg[e]);
        __syncwarp();  // xs_s reuse safety
    }
}

// ---------------------------------------------------------------------------
// Node kernel: h = agg + x@root + bias; LayerNorm; ReLU; out = h@lin_w + lin_b
// One thread per node; small weights broadcast from smem.
// ---------------------------------------------------------------------------
__global__ __launch_bounds__(256) void node_kernel(
    const float* __restrict__ x,
    const float* __restrict__ root,
    const float* __restrict__ bias,
    const float* __restrict__ norm_w,
    const float* __restrict__ norm_b,
    const float* __restrict__ lin_w,
    const float* __restrict__ lin_b,
    float* __restrict__ out)
{
    __shared__ float root_s[IN_C * HID];
    __shared__ float lw_s[HID * OUT_C];
    __shared__ float bias_s[HID], nw_s[HID], nb_s[HID], lb_s[OUT_C];

    const int tid = threadIdx.x;
    for (int i = tid; i < IN_C * HID; i += 256) root_s[i] = root[i];
    for (int i = tid; i < HID * OUT_C; i += 256) lw_s[i] = lin_w[i];
    if (tid < HID) { bias_s[tid] = bias[tid]; nw_s[tid] = norm_w[tid]; nb_s[tid] = norm_b[tid]; }
    if (tid < OUT_C) lb_s[tid] = lin_b[tid];
    __syncthreads();

    int n = blockIdx.x * blockDim.x + threadIdx.x;
    const int stride = gridDim.x * blockDim.x;
    for (; n < N_NODES; n += stride) {
        float h[HID];
        const float4* aggp = (const float4*)(g_agg + (size_t)n * HID);
        #pragma unroll
        for (int q = 0; q < HID / 4; ++q) {
            float4 v = aggp[q];
            h[q * 4 + 0] = v.x + bias_s[q * 4 + 0];
            h[q * 4 + 1] = v.y + bias_s[q * 4 + 1];
            h[q * 4 + 2] = v.z + bias_s[q * 4 + 2];
            h[q * 4 + 3] = v.w + bias_s[q * 4 + 3];
        }

        const float4* xp = (const float4*)(x + (size_t)n * IN_C);
        #pragma unroll
        for (int q = 0; q < IN_C / 4; ++q) {
            float4 xv4 = xp[q];
            float xv[4] = {xv4.x, xv4.y, xv4.z, xv4.w};
            #pragma unroll
            for (int s = 0; s < 4; ++s) {
                const int i = q * 4 + s;
                #pragma unroll
                for (int o = 0; o < HID; ++o)
                    h[o] = fmaf(xv[s], root_s[i * HID + o], h[o]);
            }
        }

        // LayerNorm over feature dim
        float mu = 0.f;
        #pragma unroll
        for (int o = 0; o < HID; ++o) mu += h[o];
        mu *= (1.0f / HID);
        float var = 0.f;
        #pragma unroll
        for (int o = 0; o < HID; ++o) { float dd = h[o] - mu; var = fmaf(dd, dd, var); }
        var *= (1.0f / HID);
        const float inv = rsqrtf(var + LN_EPS);
        #pragma unroll
        for (int o = 0; o < HID; ++o)
            h[o] = fmaxf(fmaf((h[o] - mu) * inv, nw_s[o], nb_s[o]), 0.f);  // LN + relu

        float res[OUT_C];
        #pragma unroll
        for (int oo = 0; oo < OUT_C; ++oo) res[oo] = lb_s[oo];
        #pragma unroll
        for (int k = 0; k < HID; ++k) {
            const float hv = h[k];
            #pragma unroll
            for (int oo = 0; oo < OUT_C; ++oo)
                res[oo] = fmaf(hv, lw_s[k * OUT_C + oo], res[oo]);
        }

        float4* op = (float4*)(out + (size_t)n * OUT_C);
        #pragma unroll
        for (int q = 0; q < OUT_C / 4; ++q)
            op[q] = make_float4(res[q * 4 + 0], res[q * 4 + 1], res[q * 4 + 2], res[q * 4 + 3]);
    }
}

extern "C" void kernel_launch(void* const* d_in, const int* in_sizes, int n_in,
                              void* d_out, int out_size) {
    const float* x          = (const float*)d_in[0];
    const int*   edge_index = (const int*)  d_in[1];
    const float* edge_attr  = (const float*)d_in[2];
    const float* nn_w       = (const float*)d_in[3];
    const float* nn_b       = (const float*)d_in[4];
    const float* root       = (const float*)d_in[5];
    const float* bias       = (const float*)d_in[6];
    const float* norm_w     = (const float*)d_in[7];
    const float* norm_b     = (const float*)d_in[8];
    const float* lin_w      = (const float*)d_in[9];
    const float* lin_b      = (const float*)d_in[10];
    float* out = (float*)d_out;

    zero_agg_kernel<<<256, 256>>>();
    edge_kernel<<<444, 256>>>(x, edge_index, edge_attr, nn_w, nn_b);
    node_kernel<<<(N_NODES + 255) / 256, 256>>>(x, root, bias, norm_w, norm_b,
                                                lin_w, lin_b, out);
}

// round 3
// speedup vs baseline: 1.5433x; 1.5433x over previous
#include <cuda_runtime.h>

#define N_NODES 50000
#define N_EDGES 200000
#define IN_C    32
#define HID     32
#define OUT_C   16
#define EDGE_DIM 8
#define LN_EPS  1e-5f

typedef unsigned long long u64;

__device__ float g_agg[N_NODES * HID];

__device__ __forceinline__ u64 ffma2(u64 a, u64 b, u64 c) {
    u64 d;
    asm("fma.rn.f32x2 %0, %1, %2, %3;" : "=l"(d) : "l"(a), "l"(b), "l"(c));
    return d;
}
__device__ __forceinline__ u64 dup2(float s) {
    unsigned u = __float_as_uint(s);
    return ((u64)u << 32) | (u64)u;
}
__device__ __forceinline__ u64 pack2(float lo, float hi) {
    return ((u64)__float_as_uint(hi) << 32) | (u64)__float_as_uint(lo);
}
// packed relu: clear each 32-bit half whose sign bit is set (ALU pipe)
__device__ __forceinline__ u64 relu2(u64 v) {
    unsigned lo = (unsigned)v, hi = (unsigned)(v >> 32);
    lo &= ~(unsigned)((int)lo >> 31);
    hi &= ~(unsigned)((int)hi >> 31);
    return ((u64)hi << 32) | (u64)lo;
}

__global__ __launch_bounds__(256) void zero_agg_kernel() {
    int i = blockIdx.x * blockDim.x + threadIdx.x;
    const int n4 = N_NODES * HID / 4;
    float4* p = (float4*)g_agg;
    const float4 z = make_float4(0.f, 0.f, 0.f, 0.f);
    for (; i < n4; i += gridDim.x * blockDim.x) p[i] = z;
}

// ---------------------------------------------------------------------------
// Edge kernel, f32x2-packed.
// Warp: lane l -> p = l & 15 owns output pair (2p, 2p+1); eh = l >> 4 selects
// a 4-edge subset of the warp's 8-edge group. Both half-warps read identical
// w smem words (broadcast), amortizing w LDS over 8 edges.
// smem layout: sw2[(i*8+d)*16 + p] = packed (nn_w[d][i*32+2p], ..+1)
// ---------------------------------------------------------------------------
__global__ __launch_bounds__(256) void edge_kernel(
    const float* __restrict__ x,
    const int*   __restrict__ edge_index,
    const float* __restrict__ edge_attr,
    const float* __restrict__ nn_w,
    const float* __restrict__ nn_b)
{
    __shared__ u64   sw2[IN_C * EDGE_DIM * 16];  // 4096 u64 = 32 KB
    __shared__ u64   sb2[IN_C * 16];             //  512 u64 =  4 KB
    __shared__ float xs_s[8][8][IN_C];           // warp x edge x feat = 8 KB

    const int tid = threadIdx.x;

    // stage nn_w transposed+packed: global [d][i*32 + 2p{,+1}] -> sw2[(i*8+d)*16+p]
    for (int idx = tid; idx < EDGE_DIM * 512; idx += 256) {
        const int d = idx >> 9;
        const int j = idx & 511;
        const int i = j >> 4;
        const int p = j & 15;
        const float2 v = *(const float2*)(nn_w + d * (IN_C * HID) + i * HID + 2 * p);
        sw2[(i * EDGE_DIM + d) * 16 + p] = pack2(v.x, v.y);
    }
    for (int idx = tid; idx < 512; idx += 256) {
        const int i = idx >> 4;
        const int p = idx & 15;
        const float2 v = *(const float2*)(nn_b + i * HID + 2 * p);
        sb2[i * 16 + p] = pack2(v.x, v.y);
    }
    __syncthreads();

    const int lane = tid & 31;
    const int p    = lane & 15;
    const int eh   = lane >> 4;
    const int warp = tid >> 5;
    const int gwarp = blockIdx.x * 8 + warp;
    const int warpsTotal = gridDim.x * 8;
    const int nGroups = N_EDGES / 8;  // 25000, exact

    for (int g = gwarp; g < nGroups; g += warpsTotal) {
        const int e0 = g * 8;

        // stage 8 source-node rows (coalesced; src idx broadcast via L1)
        #pragma unroll
        for (int e = 0; e < 8; ++e) {
            const int s = edge_index[e0 + e];
            xs_s[warp][e][lane] = x[(size_t)s * IN_C + lane];
        }

        // my half's 4 edges: dst + packed-duplicated edge_attr
        const int eb = e0 + eh * 4;
        int dst[4];
        u64 ea2[4][8];
        #pragma unroll
        for (int e = 0; e < 4; ++e) {
            dst[e] = edge_index[N_EDGES + eb + e];
            const float4 lo = *(const float4*)(edge_attr + (size_t)(eb + e) * EDGE_DIM);
            const float4 hi = *(const float4*)(edge_attr + (size_t)(eb + e) * EDGE_DIM + 4);
            ea2[e][0] = dup2(lo.x); ea2[e][1] = dup2(lo.y);
            ea2[e][2] = dup2(lo.z); ea2[e][3] = dup2(lo.w);
            ea2[e][4] = dup2(hi.x); ea2[e][5] = dup2(hi.y);
            ea2[e][6] = dup2(hi.z); ea2[e][7] = dup2(hi.w);
        }
        __syncwarp();

        u64 msg2[4] = {0ull, 0ull, 0ull, 0ull};

        #pragma unroll 8
        for (int i = 0; i < IN_C; ++i) {
            u64 w[8];
            #pragma unroll
            for (int d = 0; d < 8; ++d) w[d] = sw2[(i * 8 + d) * 16 + p];
            const u64 b = sb2[i * 16 + p];
            #pragma unroll
            for (int e = 0; e < 4; ++e) {
                const u64 xv = dup2(xs_s[warp][eh * 4 + e][i]);  // smem bcast
                u64 a = b;
                #pragma unroll
                for (int d = 0; d < 8; ++d) a = ffma2(ea2[e][d], w[d], a);
                a = relu2(a);                    // W[e][i][2p,2p+1]
                msg2[e] = ffma2(xv, a, msg2[e]);
            }
        }

        #pragma unroll
        for (int e = 0; e < 4; ++e) {
            float* base = &g_agg[(size_t)dst[e] * HID + 2 * p];
            atomicAdd(base,     __uint_as_float((unsigned)msg2[e]));
            atomicAdd(base + 1, __uint_as_float((unsigned)(msg2[e] >> 32)));
        }
        __syncwarp();  // xs_s reuse safety
    }
}

// ---------------------------------------------------------------------------
// Node kernel: h = agg + x@root + bias; LayerNorm; ReLU; out = h@lin_w + lin_b
// ---------------------------------------------------------------------------
__global__ __launch_bounds__(256) void node_kernel(
    const float* __restrict__ x,
    const float* __restrict__ root,
    const float* __restrict__ bias,
    const float* __restrict__ norm_w,
    const float* __restrict__ norm_b,
    const float* __restrict__ lin_w,
    const float* __restrict__ lin_b,
    float* __restrict__ out)
{
    __shared__ float root_s[IN_C * HID];
    __shared__ float lw_s[HID * OUT_C];
    __shared__ float bias_s[HID], nw_s[HID], nb_s[HID], lb_s[OUT_C];

    const int tid = threadIdx.x;
    for (int i = tid; i < IN_C * HID; i += 256) root_s[i] = root[i];
    for (int i = tid; i < HID * OUT_C; i += 256) lw_s[i] = lin_w[i];
    if (tid < HID) { bias_s[tid] = bias[tid]; nw_s[tid] = norm_w[tid]; nb_s[tid] = norm_b[tid]; }
    if (tid < OUT_C) lb_s[tid] = lin_b[tid];
    __syncthreads();

    int n = blockIdx.x * blockDim.x + threadIdx.x;
    const int stride = gridDim.x * blockDim.x;
    for (; n < N_NODES; n += stride) {
        float h[HID];
        const float4* aggp = (const float4*)(g_agg + (size_t)n * HID);
        #pragma unroll
        for (int q = 0; q < HID / 4; ++q) {
            float4 v = aggp[q];
            h[q * 4 + 0] = v.x + bias_s[q * 4 + 0];
            h[q * 4 + 1] = v.y + bias_s[q * 4 + 1];
            h[q * 4 + 2] = v.z + bias_s[q * 4 + 2];
            h[q * 4 + 3] = v.w + bias_s[q * 4 + 3];
        }

        const float4* xp = (const float4*)(x + (size_t)n * IN_C);
        #pragma unroll
        for (int q = 0; q < IN_C / 4; ++q) {
            float4 xv4 = xp[q];
            float xv[4] = {xv4.x, xv4.y, xv4.z, xv4.w};
            #pragma unroll
            for (int s = 0; s < 4; ++s) {
                const int i = q * 4 + s;
                #pragma unroll
                for (int o = 0; o < HID; ++o)
                    h[o] = fmaf(xv[s], root_s[i * HID + o], h[o]);
            }
        }

        float mu = 0.f;
        #pragma unroll
        for (int o = 0; o < HID; ++o) mu += h[o];
        mu *= (1.0f / HID);
        float var = 0.f;
        #pragma unroll
        for (int o = 0; o < HID; ++o) { float dd = h[o] - mu; var = fmaf(dd, dd, var); }
        var *= (1.0f / HID);
        const float inv = rsqrtf(var + LN_EPS);
        #pragma unroll
        for (int o = 0; o < HID; ++o)
            h[o] = fmaxf(fmaf((h[o] - mu) * inv, nw_s[o], nb_s[o]), 0.f);

        float res[OUT_C];
        #pragma unroll
        for (int oo = 0; oo < OUT_C; ++oo) res[oo] = lb_s[oo];
        #pragma unroll
        for (int k = 0; k < HID; ++k) {
            const float hv = h[k];
            #pragma unroll
            for (int oo = 0; oo < OUT_C; ++oo)
                res[oo] = fmaf(hv, lw_s[k * OUT_C + oo], res[oo]);
        }

        float4* op = (float4*)(out + (size_t)n * OUT_C);
        #pragma unroll
        for (int q = 0; q < OUT_C / 4; ++q)
            op[q] = make_float4(res[q * 4 + 0], res[q * 4 + 1], res[q * 4 + 2], res[q * 4 + 3]);
    }
}

extern "C" void kernel_launch(void* const* d_in, const int* in_sizes, int n_in,
                              void* d_out, int out_size) {
    const float* x          = (const float*)d_in[0];
    const int*   edge_index = (const int*)  d_in[1];
    const float* edge_attr  = (const float*)d_in[2];
    const float* nn_w       = (const float*)d_in[3];
    const float* nn_b       = (const float*)d_in[4];
    const float* root       = (const float*)d_in[5];
    const float* bias       = (const float*)d_in[6];
    const float* norm_w     = (const float*)d_in[7];
    const float* norm_b     = (const float*)d_in[8];
    const float* lin_w      = (const float*)d_in[9];
    const float* lin_b      = (const float*)d_in[10];
    float* out = (float*)d_out;

    zero_agg_kernel<<<296, 256>>>();
    edge_kernel<<<592, 256>>>(x, edge_index, edge_attr, nn_w, nn_b);
    node_kernel<<<(N_NODES + 255) / 256, 256>>>(x, root, bias, norm_w, norm_b,
                                                lin_w, lin_b, out);
}